// round 11
// baseline (speedup 1.0000x reference)
#include <cuda_runtime.h>
#include <cuda_bf16.h>
#include <math_constants.h>

#define BB 512
#define QQ 100
#define CC 81
#define VV 117
#define NQ (BB*QQ)

// Output layout (flattened tuple, float32):
// hoi_scores [B,Q,V] | obj_labels [B,Q] | sub_boxes [B,Q,4] | obj_boxes [B,Q,4] | keep [B,Q]
#define OFF_HOI  0ull
#define OFF_LAB  ((unsigned long long)NQ * VV)
#define OFF_SUB  (OFF_LAB + (unsigned long long)NQ)
#define OFF_OBJ  (OFF_SUB + (unsigned long long)NQ * 4)
#define OFF_KEEP (OFF_OBJ + (unsigned long long)NQ * 4)

// Scratch
__device__ float g_maxsc[NQ];
__device__ float g_cmatT[CC * VV];   // transposed correct_mat: [C][V]
__device__ int   g_tdone = 0;        // transpose-done counter (0 at rest;
                                     // k1 brings it to TBLK, k2 resets to 0)

#define TBLK 38                      // transpose blocks prepended to k1 grid

// ---------------------------------------------------------------------------
// Kernel 1: fused transpose + per-query scoring/boxes.
// Blocks [0, TBLK): transpose correct_mat, publish via counter.
// Blocks [TBLK, ...): one warp per query; spin on counter only right before
// the cmatT read (softmax phase overlaps the wait).
// ---------------------------------------------------------------------------
__global__ __launch_bounds__(256)
void k1_score(const float* __restrict__ obj_logits,
              const float* __restrict__ verb_logits,
              const float* __restrict__ sub_in,
              const float* __restrict__ obj_in,
              const float* __restrict__ cmat,     // [V, C]
              const int* __restrict__ ts,         // [B, 2] (h, w) int32
              float* __restrict__ out)
{
    // ----------------- transpose producer blocks -----------------
    if (blockIdx.x < TBLK) {
        int idx = blockIdx.x * 256 + threadIdx.x;
        if (idx < CC * VV) {
            int c = idx / VV;
            int v = idx - c * VV;
            g_cmatT[idx] = cmat[v * CC + c];
        }
        __syncthreads();
        if (threadIdx.x == 0) {
            __threadfence();
            atomicAdd(&g_tdone, 1);
        }
        return;
    }

    // ----------------- worker blocks: warp-per-query -----------------
    const int warp = threadIdx.x >> 5;
    const int lane = threadIdx.x & 31;
    const int gq = (blockIdx.x - TBLK) * 8 + warp;
    if (gq >= NQ) return;
    const int b = gq / QQ;

    // ---- softmax over 81 obj logits; max/argmax over first 80 ----
    const float* ol = obj_logits + (size_t)gq * CC;
    float l0 = ol[lane];
    float l1 = (lane + 32 < CC) ? ol[lane + 32] : -CUDART_INF_F;
    float l2 = (lane + 64 < CC) ? ol[lane + 64] : -CUDART_INF_F;

    float m = fmaxf(l0, fmaxf(l1, l2));
    #pragma unroll
    for (int o = 16; o; o >>= 1) m = fmaxf(m, __shfl_xor_sync(0xffffffffu, m, o));

    float s = __expf(l0 - m);
    if (lane + 32 < CC) s += __expf(l1 - m);
    if (lane + 64 < CC) s += __expf(l2 - m);
    #pragma unroll
    for (int o = 16; o; o >>= 1) s += __shfl_xor_sync(0xffffffffu, s, o);

    // argmax over classes [0, 80)
    float bv = l0; int bi = lane;
    if (lane + 32 < CC - 1 && l1 > bv) { bv = l1; bi = lane + 32; }
    if (lane + 64 < CC - 1 && l2 > bv) { bv = l2; bi = lane + 64; }
    #pragma unroll
    for (int o = 16; o; o >>= 1) {
        float ov = __shfl_xor_sync(0xffffffffu, bv, o);
        int   oi = __shfl_xor_sync(0xffffffffu, bi, o);
        if (ov > bv || (ov == bv && oi < bi)) { bv = ov; bi = oi; }
    }
    const float obj_score = __fdividef(__expf(bv - m), s);
    const int   label = bi;

    // ---- wait for cmatT (usually already done except first wave) ----
    if (lane == 0) {
        volatile int* d = &g_tdone;
        while (*d < TBLK) __nanosleep(100);
    }
    __syncwarp();

    // ---- hoi scores = sigmoid(verb) * obj_score * cmatT[label][v] ----
    const float* vl = verb_logits + (size_t)gq * VV;
    const float* cm = g_cmatT + (size_t)label * VV;
    float* ho = out + OFF_HOI + (size_t)gq * VV;
    float mx = -CUDART_INF_F;
    #pragma unroll
    for (int v = lane; v < VV; v += 32) {
        float e = __expf(-vl[v]);
        float sig = __fdividef(1.0f, 1.0f + e);
        float h = sig * obj_score * cm[v];
        ho[v] = h;
        mx = fmaxf(mx, h);
    }
    #pragma unroll
    for (int o = 16; o; o >>= 1) mx = fmaxf(mx, __shfl_xor_sync(0xffffffffu, mx, o));

    if (lane == 0) {
        g_maxsc[gq] = mx;
        out[OFF_LAB + gq] = (float)label;
    }

    // ---- boxes: cxcywh -> xyxy, * [w,h,w,h] ----
    if (lane < 8) {
        const int kk = lane & 3;
        const float* bx = ((lane < 4) ? sub_in : obj_in) + (size_t)gq * 4;
        float c = bx[kk & 1];
        float d = bx[(kk & 1) + 2];
        float sc = (kk & 1) ? (float)ts[b * 2 + 0] : (float)ts[b * 2 + 1];
        float val = ((kk < 2) ? (c - 0.5f * d) : (c + 0.5f * d)) * sc;
        out[((lane < 4) ? OFF_SUB : OFF_OBJ) + (size_t)gq * 4 + kk] = val;
    }
}

// ---------------------------------------------------------------------------
// Kernel 2: per-image NMS, one block (256 threads = 8 warps) per image.
// Also resets g_tdone (block 0) for the next graph replay.
// ---------------------------------------------------------------------------
__global__ __launch_bounds__(256, 4)
void k2_nms(float* __restrict__ out)
{
    const int b    = blockIdx.x;
    const int tid  = threadIdx.x;
    const int wid  = tid >> 5;
    const int lane = tid & 31;

    if (b == 0 && tid == 0) g_tdone = 0;   // replay-safe reset (k1 fully done)

    __shared__ float sc[QQ];
    __shared__ short rpart[2][QQ];
    __shared__ int   s_orig[QQ];
    __shared__ int   r_lab[QQ];
    __shared__ float r_s[5][QQ];           // sorted sub: x1,y1,x2,y2,area
    __shared__ float r_o[5][QQ];           // sorted obj
    __shared__ unsigned lmask[CC][4];      // per-label bitmask of sorted positions
    __shared__ uint4 supmat4[QQ];
    __shared__ unsigned suppw[4];

    if (tid < QQ) sc[tid] = g_maxsc[b * QQ + tid];
    for (int t = tid; t < CC * 4; t += 256) ((unsigned*)lmask)[t] = 0u;
    __syncthreads();

    // ---- stable descending rank, j-range split across two groups ----
    {
        int g = (tid >= 128);
        int q = g ? tid - 128 : tid;
        if (q < QQ) {
            float mine = sc[q];
            int r = 0;
            int j0 = g ? 50 : 0, j1 = g ? QQ : 50;
            #pragma unroll 5
            for (int j = j0; j < j1; j++) {
                float o = sc[j];
                r += (o > mine) || (o == mine && j < q);
            }
            rpart[g][q] = (short)r;
        }
    }
    __syncthreads();

    // ---- scatter into sorted order + build label mask table ----
    if (tid < QQ) {
        int r = rpart[0][tid] + rpart[1][tid];
        const size_t base = (size_t)(b * QQ + tid);
        float4 sb = *(const float4*)(out + OFF_SUB + base * 4);
        float4 ob = *(const float4*)(out + OFF_OBJ + base * 4);
        r_s[0][r] = sb.x; r_s[1][r] = sb.y; r_s[2][r] = sb.z; r_s[3][r] = sb.w;
        r_s[4][r] = (sb.z - sb.x + 1.0f) * (sb.w - sb.y + 1.0f);
        r_o[0][r] = ob.x; r_o[1][r] = ob.y; r_o[2][r] = ob.z; r_o[3][r] = ob.w;
        r_o[4][r] = (ob.z - ob.x + 1.0f) * (ob.w - ob.y + 1.0f);
        int labv = (int)out[OFF_LAB + base];
        r_lab[r]  = labv;
        s_orig[r] = tid;
        atomicOr(&lmask[labv][r >> 5], 1u << (r & 31));
    }
    __syncthreads();

    // ---- lane-owned sorted columns j = lane + 32k in registers ----
    float jsx1[4], jsy1[4], jsx2[4], jsy2[4], jsA[4];
    float jox1[4], joy1[4], jox2[4], joy2[4], joA[4];
    #pragma unroll
    for (int k = 0; k < 4; k++) {
        int j = lane + 32 * k;
        if (j < QQ) {
            jsx1[k] = r_s[0][j]; jsy1[k] = r_s[1][j]; jsx2[k] = r_s[2][j];
            jsy2[k] = r_s[3][j]; jsA[k]  = r_s[4][j];
            jox1[k] = r_o[0][j]; joy1[k] = r_o[1][j]; jox2[k] = r_o[2][j];
            joy2[k] = r_o[3][j]; joA[k]  = r_o[4][j];
        } else {
            jsx1[k]=jsy1[k]=jsx2[k]=jsy2[k]=jsA[k]=0.f;
            jox1[k]=joy1[k]=jox2[k]=joy2[k]=joA[k]=0.f;
        }
    }

    // ---- build suppression rows; label masks instead of label ballots ----
    for (int i = wid; i < QQ; i += 8) {
        int il = r_lab[i];
        uint4 lm = *(const uint4*)&lmask[il][0];   // broadcast LDS.128
        unsigned words[4];
        #pragma unroll
        for (int k = 0; k < 4; k++) {
            int d = i - 32 * k;
            unsigned gt = (d < 0) ? 0xFFFFFFFFu
                        : ((d >= 31) ? 0u : ~((2u << d) - 1u));
            unsigned lw = (k == 0) ? lm.x : (k == 1) ? lm.y : (k == 2) ? lm.z : lm.w;
            words[k] = lw & gt;
        }
        if (words[0] | words[1] | words[2] | words[3]) {
            float ix1 = r_s[0][i], iy1 = r_s[1][i], ix2 = r_s[2][i], iy2 = r_s[3][i], iA = r_s[4][i];
            float px1 = r_o[0][i], py1 = r_o[1][i], px2 = r_o[2][i], py2 = r_o[3][i], pA = r_o[4][i];
            #pragma unroll
            for (int k = 0; k < 4; k++) {
                if (words[k]) {    // warp-uniform gate
                    float w = fmaxf(0.0f, fminf(ix2, jsx2[k]) - fmaxf(ix1, jsx1[k]) + 1.0f);
                    float h = fmaxf(0.0f, fminf(iy2, jsy2[k]) - fmaxf(iy1, jsy1[k]) + 1.0f);
                    float is = w * h;
                    float us = iA + jsA[k] - is;
                    float w2 = fmaxf(0.0f, fminf(px2, jox2[k]) - fmaxf(px1, jox1[k]) + 1.0f);
                    float h2 = fmaxf(0.0f, fminf(py2, joy2[k]) - fmaxf(py1, joy1[k]) + 1.0f);
                    float io = w2 * h2;
                    float uo = pA + joA[k] - io;
                    bool pred = (is * is) * io > 0.49f * (us * us) * uo;
                    words[k] &= __ballot_sync(0xffffffffu, pred);
                }
            }
        }
        if (lane == 0)
            supmat4[i] = make_uint4(words[0], words[1], words[2], words[3]);
    }
    __syncthreads();

    // ---- sequential greedy suppression (1 thread, prefetched rows) ----
    if (tid == 0) {
        unsigned w0 = 0, w1 = 0, w2 = 0, w3 = 0;
        uint4 row = supmat4[0];
        #pragma unroll 4
        for (int i = 0; i < QQ; i++) {
            uint4 next = (i + 1 < QQ) ? supmat4[i + 1] : make_uint4(0,0,0,0);
            unsigned wi = (i < 32) ? w0 : (i < 64) ? w1 : (i < 96) ? w2 : w3;
            if (!((wi >> (i & 31)) & 1u)) {
                w0 |= row.x; w1 |= row.y; w2 |= row.z; w3 |= row.w;
            }
            row = next;
        }
        suppw[0] = w0; suppw[1] = w1; suppw[2] = w2; suppw[3] = w3;
    }
    __syncthreads();

    if (tid < QQ) {
        bool suppressed = (suppw[tid >> 5] >> (tid & 31)) & 1u;
        out[OFF_KEEP + b * QQ + s_orig[tid]] = suppressed ? 0.0f : 1.0f;
    }
}

// ---------------------------------------------------------------------------
extern "C" void kernel_launch(void* const* d_in, const int* in_sizes, int n_in,
                              void* d_out, int out_size)
{
    const float* obj_logits  = (const float*)d_in[0];
    const float* verb_logits = (const float*)d_in[1];
    const float* sub_boxes   = (const float*)d_in[2];
    const float* obj_boxes   = (const float*)d_in[3];
    const float* correct_mat = (const float*)d_in[4];
    const int*   target_sz   = (const int*)d_in[5];
    float* out = (float*)d_out;

    k1_score<<<TBLK + NQ / 8, 256>>>(obj_logits, verb_logits, sub_boxes,
                                     obj_boxes, correct_mat, target_sz, out);
    k2_nms<<<BB, 256>>>(out);
}

// round 12
// speedup vs baseline: 1.4540x; 1.4540x over previous
#include <cuda_runtime.h>
#include <cuda_bf16.h>
#include <math_constants.h>

#define BB 512
#define QQ 100
#define CC 81
#define VV 117
#define NQ (BB*QQ)

// Output layout (flattened tuple, float32):
// hoi_scores [B,Q,V] | obj_labels [B,Q] | sub_boxes [B,Q,4] | obj_boxes [B,Q,4] | keep [B,Q]
#define OFF_HOI  0ull
#define OFF_LAB  ((unsigned long long)NQ * VV)
#define OFF_SUB  (OFF_LAB + (unsigned long long)NQ)
#define OFF_OBJ  (OFF_SUB + (unsigned long long)NQ * 4)
#define OFF_KEEP (OFF_OBJ + (unsigned long long)NQ * 4)

// Scratch
__device__ float g_maxsc[NQ];
__device__ float g_cmatT[CC * VV];   // transposed correct_mat: [C][V]

// ---------------------------------------------------------------------------
// Kernel 0: transpose correct_mat [V,C] -> [C,V]. Coalesced reads,
// scattered stores (stores are fire-and-forget).
// ---------------------------------------------------------------------------
__global__ void k0_transpose(const float* __restrict__ cmat)
{
    int idx = blockIdx.x * 256 + threadIdx.x;   // idx = v*CC + c
    if (idx < CC * VV) {
        int v = idx / CC;
        int c = idx - v * CC;
        g_cmatT[c * VV + v] = cmat[idx];
    }
}

// ---------------------------------------------------------------------------
// Kernel 1: per-query scoring + boxes. One warp per query, 8 warps per block.
// ---------------------------------------------------------------------------
__global__ __launch_bounds__(256)
void k1_score(const float* __restrict__ obj_logits,
              const float* __restrict__ verb_logits,
              const float* __restrict__ sub_in,
              const float* __restrict__ obj_in,
              const int* __restrict__ ts,         // [B, 2] (h, w) int32
              float* __restrict__ out)
{
    const int warp = threadIdx.x >> 5;
    const int lane = threadIdx.x & 31;
    const int gq = blockIdx.x * 8 + warp;
    if (gq >= NQ) return;
    const int b = gq / QQ;

    // ---- softmax over 81 obj logits; max/argmax over first 80 ----
    const float* ol = obj_logits + (size_t)gq * CC;
    float l0 = ol[lane];
    float l1 = (lane + 32 < CC) ? ol[lane + 32] : -CUDART_INF_F;
    float l2 = (lane + 64 < CC) ? ol[lane + 64] : -CUDART_INF_F;

    float m = fmaxf(l0, fmaxf(l1, l2));
    #pragma unroll
    for (int o = 16; o; o >>= 1) m = fmaxf(m, __shfl_xor_sync(0xffffffffu, m, o));

    float s = __expf(l0 - m);
    if (lane + 32 < CC) s += __expf(l1 - m);
    if (lane + 64 < CC) s += __expf(l2 - m);
    #pragma unroll
    for (int o = 16; o; o >>= 1) s += __shfl_xor_sync(0xffffffffu, s, o);

    // argmax over classes [0, 80)
    float bv = l0; int bi = lane;
    if (lane + 32 < CC - 1 && l1 > bv) { bv = l1; bi = lane + 32; }
    if (lane + 64 < CC - 1 && l2 > bv) { bv = l2; bi = lane + 64; }
    #pragma unroll
    for (int o = 16; o; o >>= 1) {
        float ov = __shfl_xor_sync(0xffffffffu, bv, o);
        int   oi = __shfl_xor_sync(0xffffffffu, bi, o);
        if (ov > bv || (ov == bv && oi < bi)) { bv = ov; bi = oi; }
    }
    const float obj_score = __fdividef(__expf(bv - m), s);
    const int   label = bi;

    // ---- hoi scores = sigmoid(verb) * obj_score * cmatT[label][v] ----
    const float* vl = verb_logits + (size_t)gq * VV;
    const float* cm = g_cmatT + (size_t)label * VV;
    float* ho = out + OFF_HOI + (size_t)gq * VV;
    float mx = -CUDART_INF_F;
    #pragma unroll
    for (int v = lane; v < VV; v += 32) {
        float e = __expf(-vl[v]);
        float sig = __fdividef(1.0f, 1.0f + e);
        float h = sig * obj_score * cm[v];
        ho[v] = h;
        mx = fmaxf(mx, h);
    }
    #pragma unroll
    for (int o = 16; o; o >>= 1) mx = fmaxf(mx, __shfl_xor_sync(0xffffffffu, mx, o));

    if (lane == 0) {
        g_maxsc[gq] = mx;
        out[OFF_LAB + gq] = (float)label;
    }

    // ---- boxes: cxcywh -> xyxy, * [w,h,w,h] ----
    if (lane < 8) {
        const int kk = lane & 3;
        const float* bx = ((lane < 4) ? sub_in : obj_in) + (size_t)gq * 4;
        float c = bx[kk & 1];
        float d = bx[(kk & 1) + 2];
        float sc = (kk & 1) ? (float)ts[b * 2 + 0] : (float)ts[b * 2 + 1];
        float val = ((kk < 2) ? (c - 0.5f * d) : (c + 0.5f * d)) * sc;
        out[((lane < 4) ? OFF_SUB : OFF_OBJ) + (size_t)gq * 4 + kk] = val;
    }
}

// ---------------------------------------------------------------------------
// Kernel 2: per-image NMS with PAIR COMPACTION.
// Only same-label pairs (expected ~62 of 4950) get IoU evaluation.
// ---------------------------------------------------------------------------
#define MAXP (QQ*(QQ-1)/2)   // 4950, worst case all labels equal

__global__ __launch_bounds__(256, 4)
void k2_nms(float* __restrict__ out)
{
    const int b   = blockIdx.x;
    const int tid = threadIdx.x;

    __shared__ float sc[QQ];
    __shared__ short rpart[2][QQ];
    __shared__ int   s_orig[QQ];
    __shared__ int   r_lab[QQ];
    __shared__ float r_s[5][QQ];           // sorted sub: x1,y1,x2,y2,area
    __shared__ float r_o[5][QQ];           // sorted obj
    __shared__ unsigned lmask[CC][4];      // per-label bitmask of sorted positions
    __shared__ unsigned supmat[QQ][4];
    __shared__ unsigned suppw[4];
    __shared__ int npairs;
    __shared__ ushort2 plist[MAXP];

    if (tid < QQ) sc[tid] = g_maxsc[b * QQ + tid];
    for (int t = tid; t < CC * 4; t += 256) ((unsigned*)lmask)[t] = 0u;
    for (int t = tid; t < QQ * 4; t += 256) ((unsigned*)supmat)[t] = 0u;
    if (tid == 0) npairs = 0;
    __syncthreads();

    // ---- stable descending rank, j-range split across two groups ----
    {
        int g = (tid >= 128);
        int q = g ? tid - 128 : tid;
        if (q < QQ) {
            float mine = sc[q];
            int r = 0;
            int j0 = g ? 50 : 0, j1 = g ? QQ : 50;
            #pragma unroll 5
            for (int j = j0; j < j1; j++) {
                float o = sc[j];
                r += (o > mine) || (o == mine && j < q);
            }
            rpart[g][q] = (short)r;
        }
    }
    __syncthreads();

    // ---- scatter into sorted order + build label mask table ----
    if (tid < QQ) {
        int r = rpart[0][tid] + rpart[1][tid];
        const size_t base = (size_t)(b * QQ + tid);
        float4 sb = *(const float4*)(out + OFF_SUB + base * 4);
        float4 ob = *(const float4*)(out + OFF_OBJ + base * 4);
        r_s[0][r] = sb.x; r_s[1][r] = sb.y; r_s[2][r] = sb.z; r_s[3][r] = sb.w;
        r_s[4][r] = (sb.z - sb.x + 1.0f) * (sb.w - sb.y + 1.0f);
        r_o[0][r] = ob.x; r_o[1][r] = ob.y; r_o[2][r] = ob.z; r_o[3][r] = ob.w;
        r_o[4][r] = (ob.z - ob.x + 1.0f) * (ob.w - ob.y + 1.0f);
        int labv = (int)out[OFF_LAB + base];
        r_lab[r]  = labv;
        s_orig[r] = tid;
        atomicOr(&lmask[labv][r >> 5], 1u << (r & 31));
    }
    __syncthreads();

    // ---- compact same-label (i, j>i) pairs into a worklist ----
    if (tid < QQ) {
        const int i = tid;
        const unsigned* lm = lmask[r_lab[i]];
        unsigned w[4];
        #pragma unroll
        for (int k = 0; k < 4; k++) {
            int d = i - 32 * k;
            unsigned gt = (d < 0) ? 0xFFFFFFFFu
                        : ((d >= 31) ? 0u : ~((2u << d) - 1u));
            w[k] = lm[k] & gt;
        }
        int nb = __popc(w[0]) + __popc(w[1]) + __popc(w[2]) + __popc(w[3]);
        if (nb) {
            int off = atomicAdd(&npairs, nb);
            #pragma unroll
            for (int k = 0; k < 4; k++) {
                unsigned word = w[k];
                while (word) {
                    int bit = __ffs(word) - 1;
                    word &= word - 1;
                    plist[off++] = make_ushort2((unsigned short)i,
                                                (unsigned short)(32 * k + bit));
                }
            }
        }
    }
    __syncthreads();

    // ---- evaluate pairs (expected ~62 per image) ----
    const int np = npairs;
    for (int p = tid; p < np; p += 256) {
        ushort2 pr = plist[p];
        int i = pr.x, j = pr.y;
        // sub IoU terms
        float w  = fmaxf(0.0f, fminf(r_s[2][i], r_s[2][j]) - fmaxf(r_s[0][i], r_s[0][j]) + 1.0f);
        float h  = fmaxf(0.0f, fminf(r_s[3][i], r_s[3][j]) - fmaxf(r_s[1][i], r_s[1][j]) + 1.0f);
        float is = w * h;
        float us = r_s[4][i] + r_s[4][j] - is;
        // obj IoU terms
        float w2 = fmaxf(0.0f, fminf(r_o[2][i], r_o[2][j]) - fmaxf(r_o[0][i], r_o[0][j]) + 1.0f);
        float h2 = fmaxf(0.0f, fminf(r_o[3][i], r_o[3][j]) - fmaxf(r_o[1][i], r_o[1][j]) + 1.0f);
        float io = w2 * h2;
        float uo = r_o[4][i] + r_o[4][j] - io;
        // (is/us)*sqrt(io/uo) > 0.7  <=>  is^2*io > 0.49*us^2*uo
        if ((is * is) * io > 0.49f * (us * us) * uo)
            atomicOr(&supmat[i][j >> 5], 1u << (j & 31));
    }
    __syncthreads();

    // ---- sequential greedy suppression (1 thread, prefetched rows) ----
    if (tid == 0) {
        unsigned w0 = 0, w1 = 0, w2 = 0, w3 = 0;
        if (np) {
            uint4 row = *(const uint4*)&supmat[0][0];
            #pragma unroll 4
            for (int i = 0; i < QQ; i++) {
                uint4 next = (i + 1 < QQ) ? *(const uint4*)&supmat[i + 1][0]
                                          : make_uint4(0,0,0,0);
                unsigned wi = (i < 32) ? w0 : (i < 64) ? w1 : (i < 96) ? w2 : w3;
                if (!((wi >> (i & 31)) & 1u)) {
                    w0 |= row.x; w1 |= row.y; w2 |= row.z; w3 |= row.w;
                }
                row = next;
            }
        }
        suppw[0] = w0; suppw[1] = w1; suppw[2] = w2; suppw[3] = w3;
    }
    __syncthreads();

    if (tid < QQ) {
        bool suppressed = (suppw[tid >> 5] >> (tid & 31)) & 1u;
        out[OFF_KEEP + b * QQ + s_orig[tid]] = suppressed ? 0.0f : 1.0f;
    }
}

// ---------------------------------------------------------------------------
extern "C" void kernel_launch(void* const* d_in, const int* in_sizes, int n_in,
                              void* d_out, int out_size)
{
    const float* obj_logits  = (const float*)d_in[0];
    const float* verb_logits = (const float*)d_in[1];
    const float* sub_boxes   = (const float*)d_in[2];
    const float* obj_boxes   = (const float*)d_in[3];
    const float* correct_mat = (const float*)d_in[4];
    const int*   target_sz   = (const int*)d_in[5];
    float* out = (float*)d_out;

    k0_transpose<<<(CC * VV + 255) / 256, 256>>>(correct_mat);
    k1_score<<<NQ / 8, 256>>>(obj_logits, verb_logits, sub_boxes, obj_boxes,
                              target_sz, out);
    k2_nms<<<BB, 256>>>(out);
}